// round 9
// baseline (speedup 1.0000x reference)
#include <cuda_runtime.h>
#include <cstdint>

#define EMB    1024
#define HID    128
#define PW     64
#define KSEG   2112          // g_W1T cols: bm(1024) + sim(1024) + pw(64) = W1 rows [1024,3136)
#define NCHUNK 34            // 32 e-chunks (K=32, sim folded into B) + 2 pw chunks
#define EPSV   1e-7f

// -------------------- device scratch (no allocs allowed) --------------------
__device__ float g_W1T[HID * KSEG];   // g_W1T[n][32-blk b][perm pos] = tf32(W1[1024+32b+k][n])
__device__ int   g_idx64;

// -------------------- helpers --------------------
__device__ __forceinline__ uint32_t smem_u32(const void* p) {
    uint32_t a;
    asm("{ .reg .u64 t; cvta.to.shared.u64 t, %1; cvt.u32.u64 %0, t; }" : "=r"(a) : "l"(p));
    return a;
}
__device__ __forceinline__ unsigned long long to_global(const void* p) {
    unsigned long long g;
    asm("cvta.to.global.u64 %0, %1;" : "=l"(g) : "l"(p));
    return g;
}
#define CP16(dst_s32, src_g64) \
    asm volatile("cp.async.cg.shared.global [%0], [%1], 16;" :: "r"(dst_s32), "l"(src_g64) : "memory")
#define CP_COMMIT() asm volatile("cp.async.commit_group;" ::: "memory")
#define CP_WAIT1()  asm volatile("cp.async.wait_group 1;" ::: "memory")

__device__ __forceinline__ void mma_tf32(float c[4], uint32_t a0, uint32_t a1, uint32_t a2, uint32_t a3,
                                         uint32_t b0, uint32_t b1) {
    asm volatile("mma.sync.aligned.m16n8k8.row.col.f32.tf32.tf32.f32 "
                 "{%0,%1,%2,%3}, {%4,%5,%6,%7}, {%8,%9}, {%0,%1,%2,%3};"
                 : "+f"(c[0]), "+f"(c[1]), "+f"(c[2]), "+f"(c[3])
                 : "r"(a0), "r"(a1), "r"(a2), "r"(a3), "r"(b0), "r"(b1));
}
__device__ __forceinline__ int load_idx(const void* p, size_t pos, int is64) {
    return is64 ? (int)((const long long*)p)[pos] : ((const int*)p)[pos];
}

// -------------------- W1 transpose + tf32 round + t-major permute (+ idx detect) ----------------
// g_W1T[n][kb + perm(k)] = rna(W1[1024+kb+k][n]);  perm(k) = 8*(k&3) + 2*(k>>3) + ((k>>2)&1)
__global__ __launch_bounds__(256)
void transpose_w1_kernel(const float* __restrict__ W1,
                         const unsigned* __restrict__ idxw, int n_words) {
    __shared__ float s[32][33];
    const int kb = blockIdx.x * 32, nb = blockIdx.y * 32;
    const int tx = threadIdx.x & 31, ty = threadIdx.x >> 5;
    if (blockIdx.x == 0 && blockIdx.y == 0 && threadIdx.x == 0) {
        unsigned acc = 0;
        int m = n_words < 256 ? n_words : 256;
        for (int i = 1; i < m; i += 2) acc |= idxw[i];
        g_idx64 = (acc == 0u) ? 1 : 0;
    }
#pragma unroll
    for (int j = 0; j < 4; j++) {
        int k = ty + 8 * j;
        s[k][tx] = W1[(size_t)(1024 + kb + k) * HID + nb + tx];
    }
    __syncthreads();
#pragma unroll
    for (int j = 0; j < 4; j++) {
        int y = ty + 8 * j;
        float v = s[tx][y];
        uint32_t tv;
        asm("cvt.rna.tf32.f32 %0, %1;" : "=r"(tv) : "f"(v));
        int pk = 8 * (tx & 3) + 2 * (tx >> 3) + ((tx >> 2) & 1);
        g_W1T[(size_t)(nb + y) * KSEG + kb + pk] = __uint_as_float(tv);
    }
}

// -------------------- fused pair kernel --------------------
// Block: 2 batch rows -> M=128, N=128, 256 threads / 8 warps; 2 CTAs co-resident per SM.
// Warp (mi = wid&1, nh = wid>>1): rows [64mi, 64mi+64), cols [32nh, 32nh+32); bq == mi.
// B'' = WB + am (.) WS folded in registers. aproj interleaved via coalesced LDG.
#define OFF_IDX    0                     // 128 ints
#define OFF_WOUT   512                   // 128 f
#define OFF_APROJ  1024                  // 256 f
#define OFF_STAGE  2048
#define ST_A       0                     // 128 rows x 36 f (144B rows), plain k layout
#define ST_AM      18432                 // 2 x 36 f, plain
#define ST_WB      18720                 // 128 x 36 f, t-major permuted
#define ST_WS      37152                 // 128 x 36 f, t-major permuted
#define STAGE_B    55584
#define SMEM_TOTAL (OFF_STAGE + 2 * STAGE_B)   // 113216 -> 2 CTAs/SM

struct StageCtx {
    unsigned long long all_m_g, w1t_g, pw_g, mb_g;
    int b0, n_ants;
};

__device__ __forceinline__ void stage_chunk(int c, uint32_t sbase,
                                            const int* idx_s, const StageCtx& cx, int tid) {
    const uint32_t stg = sbase + OFF_STAGE + (uint32_t)(c & 1) * STAGE_B;
    if (c < 32) {
        const int ec = c * 32;
#pragma unroll
        for (int it = 0; it < 4; it++) {       // A: gathered bm rows [128][32]
            int id = tid + it * 256;
            int r = id >> 3, f4 = id & 7;
            unsigned long long src = cx.all_m_g + ((size_t)idx_s[r] * EMB + ec + f4 * 4) * 4ull;
            CP16(stg + ST_A + (uint32_t)(r * 144 + f4 * 16), src);
        }
        if (tid < 16) {                        // AM: am chunk [2][32]
            int q = tid >> 3, f4 = tid & 7;
            unsigned long long src = cx.mb_g + ((size_t)(cx.b0 + q) * EMB + ec + f4 * 4) * 4ull;
            CP16(stg + ST_AM + (uint32_t)(q * 144 + f4 * 16), src);
        }
#pragma unroll
        for (int it = 0; it < 8; it++) {       // WB / WS (permuted in gmem)
            int id = tid + it * 256;
            int seg = id >> 10, n = (id >> 3) & 127, f4 = id & 7;
            unsigned long long src = cx.w1t_g +
                ((size_t)n * KSEG + (seg ? 1024 + ec : ec) + f4 * 4) * 4ull;
            CP16(stg + (seg ? ST_WS : ST_WB) + (uint32_t)(n * 144 + f4 * 16), src);
        }
    } else {
        const int pc = (c - 32) * 32;
#pragma unroll
        for (int it = 0; it < 4; it++) {       // A: pw values [128][32]
            int id = tid + it * 256;
            int r = id >> 3, f4 = id & 7;
            int bq = r >> 6, a = r & 63; if (a >= cx.n_ants) a = cx.n_ants - 1;
            unsigned long long src = cx.pw_g +
                (((size_t)(cx.b0 + bq) * cx.n_ants + a) * PW + pc + f4 * 4) * 4ull;
            CP16(stg + ST_A + (uint32_t)(r * 144 + f4 * 16), src);
        }
#pragma unroll
        for (int it = 0; it < 4; it++) {       // B: W1p (permuted) into WB region
            int id = tid + it * 256;
            int n = id >> 3, f4 = id & 7;
            unsigned long long src = cx.w1t_g + ((size_t)n * KSEG + 2048 + pc + f4 * 4) * 4ull;
            CP16(stg + ST_WB + (uint32_t)(n * 144 + f4 * 16), src);
        }
    }
}

__global__ __launch_bounds__(256, 2)
void pair_mma_kernel(const float* __restrict__ all_m,
                     const float* __restrict__ m_b,
                     const float* __restrict__ pw,
                     const void*  __restrict__ top_idx,
                     const float* __restrict__ rough,
                     const float* __restrict__ W1,
                     const float* __restrict__ b1,
                     const float* __restrict__ W_out,
                     const float* __restrict__ b_out,
                     float* __restrict__ out,
                     int n_ants) {
    extern __shared__ char smem[];
    const uint32_t sbase = smem_u32(smem);
    const int tid  = threadIdx.x;
    const int lane = tid & 31;
    const int wid  = tid >> 5;
    const int t    = lane & 3;       // k lane within quad
    const int q    = lane >> 2;      // row/col lane (0..7)
    const int b0   = blockIdx.x * 2;
    const int mi   = wid & 1;        // m-tile: rows [64mi, 64mi+64); == bq
    const int nh   = wid >> 1;       // n-quarter: cols [32nh, 32nh+32)
    const int rb   = mi * 64, nb = nh * 32;

    int*   idx_s   = (int*)(smem + OFF_IDX);
    float* wout_s  = (float*)(smem + OFF_WOUT);
    float* aproj_s = (float*)(smem + OFF_APROJ);

    StageCtx cx;
    cx.all_m_g = to_global(all_m);
    cx.w1t_g   = to_global(g_W1T);
    cx.pw_g    = to_global(pw);
    cx.mb_g    = to_global(m_b);
    cx.b0 = b0; cx.n_ants = n_ants;

    if (tid < 128) {
        int a = tid & 63; if (a >= n_ants) a = n_ants - 1;
        idx_s[tid] = load_idx(top_idx, (size_t)(b0 + (tid >> 6)) * n_ants + a, g_idx64);
        wout_s[tid] = W_out[tid];
    }
    __syncthreads();

    stage_chunk(0, sbase, idx_s, cx, tid); CP_COMMIT();
    stage_chunk(1, sbase, idx_s, cx, tid); CP_COMMIT();

    // accumulators: 4 m-frags x 4 n-frags x 4
    float acc[4][4][4];
#pragma unroll
    for (int i = 0; i < 4; i++)
#pragma unroll
        for (int nf = 0; nf < 4; nf++)
#pragma unroll
            for (int r = 0; r < 4; r++) acc[i][nf][r] = 0.f;

    // aproj accumulator: thread owns (abq = tid>>7, an = tid&127); coalesced W1 rows
    const int abq = tid >> 7, an = tid & 127;
    const float* ap_w  = W1 + an;
    const float* ap_am = m_b + (size_t)(b0 + abq) * EMB;
    float aproj_acc = 0.f;

    for (int c = 0; c < NCHUNK; c++) {
        CP_WAIT1();
        __syncthreads();                       // stage(c) ready

        const char*  stp = smem + OFF_STAGE + (c & 1) * STAGE_B;
        const float* Ab  = (const float*)(stp + ST_A);
        const float* amr = (const float*)(stp + ST_AM) + mi * 36;
        const bool has_sim = (c < 32);

#pragma unroll
        for (int h2 = 0; h2 < 2; h2++) {       // two k16 halves per chunk
            float bpp[4][4];
            float am0, am1, am2, am3;
            if (has_sim) {
                am0 = amr[16 * h2 + t];        // (jp=0, b0)
                am1 = amr[16 * h2 + 4 + t];    // (jp=0, b1)
                am2 = amr[16 * h2 + 8 + t];    // (jp=1, b0)
                am3 = amr[16 * h2 + 12 + t];   // (jp=1, b1)
            }
#pragma unroll
            for (int nf = 0; nf < 4; nf++) {
                int n = nb + nf * 8 + q;
                float4 wb4 = *(const float4*)(stp + ST_WB + n * 144 + t * 32 + h2 * 16);
                if (has_sim) {
                    float4 ws4 = *(const float4*)(stp + ST_WS + n * 144 + t * 32 + h2 * 16);
                    bpp[nf][0] = fmaf(am0, ws4.x, wb4.x);
                    bpp[nf][1] = fmaf(am1, ws4.y, wb4.y);
                    bpp[nf][2] = fmaf(am2, ws4.z, wb4.z);
                    bpp[nf][3] = fmaf(am3, ws4.w, wb4.w);
                } else {
                    bpp[nf][0] = wb4.x; bpp[nf][1] = wb4.y;
                    bpp[nf][2] = wb4.z; bpp[nf][3] = wb4.w;
                }
            }
#pragma unroll
            for (int jp = 0; jp < 2; jp++) {
                const int k0 = 16 * h2 + 8 * jp;
                uint32_t a_[4][4];
#pragma unroll
                for (int i = 0; i < 4; i++) {
                    const float* ap = Ab + (size_t)(rb + 16 * i + q) * 36 + k0 + t;
                    a_[i][0] = __float_as_uint(ap[0]);
                    a_[i][1] = __float_as_uint(ap[8 * 36]);
                    a_[i][2] = __float_as_uint(ap[4]);
                    a_[i][3] = __float_as_uint(ap[8 * 36 + 4]);
                }
#pragma unroll
                for (int nf = 0; nf < 4; nf++) {
                    uint32_t b0r = __float_as_uint(bpp[nf][2 * jp]);
                    uint32_t b1r = __float_as_uint(bpp[nf][2 * jp + 1]);
#pragma unroll
                    for (int i = 0; i < 4; i++)
                        mma_tf32(acc[i][nf], a_[i][0], a_[i][1], a_[i][2], a_[i][3], b0r, b1r);
                }
            }
        }

        if (has_sim) {                          // interleaved aproj (coalesced LDG)
            const float* wrow = ap_w + (size_t)(c * 32) * HID;
            const float* amr2 = ap_am + c * 32;
#pragma unroll 8
            for (int kk = 0; kk < 32; kk++)
                aproj_acc += __ldg(amr2 + kk) * __ldg(wrow + (size_t)kk * HID);
        }
        __syncthreads();                        // done reading stage(c)

        if (c + 2 < NCHUNK) stage_chunk(c + 2, sbase, idx_s, cx, tid);
        CP_COMMIT();
    }

    // ---- epilogue ----
    aproj_s[tid] = aproj_acc + b1[an];          // tid == abq*128 + an
    __syncthreads();

    float* part = (float*)(smem + OFF_STAGE);   // [128][4] partials
    const float  bo  = __ldg(b_out);
    const float* apq = aproj_s + mi * 128;
#pragma unroll
    for (int i = 0; i < 4; i++) {
        float s0 = 0.f, s1 = 0.f;               // rows rb+16i+q, rb+16i+q+8
#pragma unroll
        for (int nf = 0; nf < 4; nf++) {
            int n0 = nb + nf * 8 + 2 * t, n1 = n0 + 1;
            float w0 = wout_s[n0], w1 = wout_s[n1];
            float ap0 = apq[n0], ap1 = apq[n1];
            float h;
            h = acc[i][nf][0] + ap0; h = fmaxf(h, 0.f) + 0.01f * fminf(h, 0.f); s0 += h * w0;
            h = acc[i][nf][1] + ap1; h = fmaxf(h, 0.f) + 0.01f * fminf(h, 0.f); s0 += h * w1;
            h = acc[i][nf][2] + ap0; h = fmaxf(h, 0.f) + 0.01f * fminf(h, 0.f); s1 += h * w0;
            h = acc[i][nf][3] + ap1; h = fmaxf(h, 0.f) + 0.01f * fminf(h, 0.f); s1 += h * w1;
        }
        s0 += __shfl_xor_sync(0xffffffffu, s0, 1);
        s0 += __shfl_xor_sync(0xffffffffu, s0, 2);
        s1 += __shfl_xor_sync(0xffffffffu, s1, 1);
        s1 += __shfl_xor_sync(0xffffffffu, s1, 2);
        if (t == 0) {
            part[(rb + 16 * i + q) * 4 + nh]     = s0;
            part[(rb + 16 * i + q + 8) * 4 + nh] = s1;
        }
    }
    __syncthreads();

    if (tid < 128) {
        float sc = part[tid * 4] + part[tid * 4 + 1] + part[tid * 4 + 2] + part[tid * 4 + 3];
        int a = tid & 63, bg = b0 + (tid >> 6);
        if (a < n_ants)
            out[(size_t)bg * (n_ants + 1) + 1 + a] =
                rough[(size_t)bg * n_ants + a] + bo + sc;
        if (a == 0) out[(size_t)bg * (n_ants + 1)] = EPSV;
    }
}

// -------------------- launch --------------------
extern "C" void kernel_launch(void* const* d_in, const int* in_sizes, int n_in,
                              void* d_out, int out_size) {
    const float* all_m = (const float*)d_in[0];
    const float* m_b   = (const float*)d_in[1];
    const float* pw    = (const float*)d_in[2];
    const void*  idx   = d_in[3];
    const float* rough = (const float*)d_in[4];
    const float* W1    = (const float*)d_in[5];
    const float* b1    = (const float*)d_in[6];
    const float* Wo    = (const float*)d_in[7];
    const float* bo    = (const float*)d_in[8];
    float* out = (float*)d_out;

    const int batch  = in_sizes[1] / EMB;     // 512
    const int n_ants = in_sizes[3] / batch;   // 50

    cudaFuncSetAttribute(pair_mma_kernel,
                         cudaFuncAttributeMaxDynamicSharedMemorySize, SMEM_TOTAL);

    transpose_w1_kernel<<<dim3(KSEG / 32, HID / 32), 256>>>(W1, (const unsigned*)idx,
                                                            in_sizes[3]);
    pair_mma_kernel<<<batch / 2, 256, SMEM_TOTAL>>>(all_m, m_b, pw, idx, rough,
                                                    W1, b1, Wo, bo, out, n_ants);
}

// round 10
// speedup vs baseline: 1.2545x; 1.2545x over previous
#include <cuda_runtime.h>
#include <cuda_fp16.h>
#include <cstdint>

#define EMB    1024
#define HID    128
#define PW     64
#define KSEG   2112          // W1 rows [1024,3136): bm(1024) + sim(1024) + pw(64)
#define NCHUNK 34            // 32 e-chunks (K=32, sim folded into B) + 2 pw chunks
#define EPSV   1e-7f

// -------------------- device scratch (no allocs allowed) --------------------
__device__ __half g_allm_h[10016 * EMB];   // fp16 all_mentions, plain layout
__device__ __half g_W1Th[HID * KSEG];      // fp16 W1^T, per-32-chunk fragment-permuted
__device__ __half g_amb_hp[512 * EMB];     // fp16 mentions_batch, fragment-permuted
__device__ __half g_pw_h[512 * 64 * PW];   // fp16 pw, plain
__device__ int    g_idx64;

// fragment permutation within a 32-k chunk (matches m16n8k16 B/mult layout):
// t=(k>>1)&3, hi=(k>>3)&1, b=k&1, h16=k>>4  ->  pos = t*8 + h16*4 + hi*2 + b
__device__ __forceinline__ int permk(int kk) {
    return ((kk >> 1) & 3) * 8 + (kk >> 4) * 4 + ((kk >> 3) & 1) * 2 + (kk & 1);
}

// -------------------- helpers --------------------
__device__ __forceinline__ uint32_t smem_u32(const void* p) {
    uint32_t a;
    asm("{ .reg .u64 t; cvta.to.shared.u64 t, %1; cvt.u32.u64 %0, t; }" : "=r"(a) : "l"(p));
    return a;
}
__device__ __forceinline__ unsigned long long to_global(const void* p) {
    unsigned long long g;
    asm("cvta.to.global.u64 %0, %1;" : "=l"(g) : "l"(p));
    return g;
}
#define CP16(dst_s32, src_g64) \
    asm volatile("cp.async.cg.shared.global [%0], [%1], 16;" :: "r"(dst_s32), "l"(src_g64) : "memory")
#define CP_COMMIT() asm volatile("cp.async.commit_group;" ::: "memory")
#define CP_WAIT2()  asm volatile("cp.async.wait_group 2;" ::: "memory")

__device__ __forceinline__ void mma_f16(float c[4], uint32_t a0, uint32_t a1, uint32_t a2, uint32_t a3,
                                        uint32_t b0, uint32_t b1) {
    asm volatile("mma.sync.aligned.m16n8k16.row.col.f32.f16.f16.f32 "
                 "{%0,%1,%2,%3}, {%4,%5,%6,%7}, {%8,%9}, {%0,%1,%2,%3};"
                 : "+f"(c[0]), "+f"(c[1]), "+f"(c[2]), "+f"(c[3])
                 : "r"(a0), "r"(a1), "r"(a2), "r"(a3), "r"(b0), "r"(b1));
}
__device__ __forceinline__ uint32_t hfma2u(uint32_t a, uint32_t b, uint32_t c) {
    uint32_t d;
    asm("fma.rn.f16x2 %0, %1, %2, %3;" : "=r"(d) : "r"(a), "r"(b), "r"(c));
    return d;
}
__device__ __forceinline__ int load_idx(const void* p, size_t pos, int is64) {
    return is64 ? (int)((const long long*)p)[pos] : ((const int*)p)[pos];
}

// -------------------- single prep kernel: fp16 conversions + permutes + idx detect ------------
__global__ __launch_bounds__(256)
void prep_kernel(const float* __restrict__ all_m, const float* __restrict__ m_b,
                 const float* __restrict__ pw, const float* __restrict__ W1,
                 const unsigned* __restrict__ idxw, int n_words,
                 int n_mentions, int batch, int n_ants) {
    if (blockIdx.x == 0 && threadIdx.x == 0) {
        unsigned acc = 0;
        int m = n_words < 256 ? n_words : 256;
        for (int i = 1; i < m; i += 2) acc |= idxw[i];
        g_idx64 = (acc == 0u) ? 1 : 0;
    }
    const long long n4a = (long long)n_mentions * EMB / 4;
    const long long nw1 = (long long)KSEG * HID;
    const long long nmb = (long long)batch * EMB;
    const long long npw = (long long)batch * n_ants * PW;
    const long long TOT = n4a + nw1 + nmb + npw;
    const long long stride = (long long)gridDim.x * blockDim.x;
    for (long long i = (long long)blockIdx.x * blockDim.x + threadIdx.x; i < TOT; i += stride) {
        if (i < n4a) {
            float4 v = ((const float4*)all_m)[i];
            __half2* d = (__half2*)(g_allm_h + i * 4);
            d[0] = __floats2half2_rn(v.x, v.y);
            d[1] = __floats2half2_rn(v.z, v.w);
        } else if (i < n4a + nw1) {
            long long j = i - n4a;
            int k = (int)(j / HID), n = (int)(j % HID);
            float v = W1[(size_t)(1024 + k) * HID + n];
            g_W1Th[(size_t)n * KSEG + (k & ~31) + permk(k & 31)] = __float2half_rn(v);
        } else if (i < n4a + nw1 + nmb) {
            long long j = i - n4a - nw1;
            int b = (int)(j >> 10), k = (int)(j & 1023);
            g_amb_hp[(size_t)b * EMB + (k & ~31) + permk(k & 31)] = __float2half_rn(m_b[j]);
        } else {
            long long j = i - n4a - nw1 - nmb;
            g_pw_h[j] = __float2half_rn(pw[j]);
        }
    }
}

// -------------------- fused fp16 pair kernel --------------------
// Block: 4 batch rows -> M=256, N=128, 512 threads / 16 warps, grid = batch/4 = 128.
// Warp (mi = wid&3, nh = wid>>2): rows [64mi,64mi+64), cols [32nh,32nh+32); bq == mi.
// B'' = WB + am (.) WS folded in registers (fp16). aproj fp32 LDG-interleaved.
#define OFF_IDX    0                     // 256 ints
#define OFF_WOUT   1024                  // 128 f
#define OFF_APROJ  1536                  // 512 f
#define OFF_STAGE  3584
#define ST_A       0                     // 256 rows x 80 B (32 halfs + pad)
#define ST_AM      20480                 // 4 x 64 B (permuted fp16)
#define ST_WB      20736                 // 128 x 64 B (permuted fp16)
#define ST_WS      28928                 // 128 x 64 B
#define STAGE_B    37120
#define SMEM_TOTAL (OFF_STAGE + 3 * STAGE_B)   // 114944

struct StageCtx {
    unsigned long long allm_g, w1t_g, pw_g, amb_g;
    int b0, n_ants;
};

__device__ __forceinline__ void stage_chunk(int c, uint32_t sbase,
                                            const int* idx_s, const StageCtx& cx, int tid) {
    const uint32_t stg = sbase + OFF_STAGE + (uint32_t)(c % 3) * STAGE_B;
    if (c < 32) {
        const int ec = c * 32;
#pragma unroll
        for (int it = 0; it < 2; it++) {       // A: gathered bm rows [256][32] fp16
            int id = tid + it * 512;
            int r = id >> 2, f4 = id & 3;
            unsigned long long src = cx.allm_g + ((size_t)idx_s[r] * EMB + ec) * 2ull + f4 * 16;
            CP16(stg + ST_A + (uint32_t)(r * 80 + f4 * 16), src);
        }
#pragma unroll
        for (int it = 0; it < 2; it++) {       // WB / WS (permuted fp16)
            int id = tid + it * 512;
            int seg = id >> 9, n = (id >> 2) & 127, f4 = id & 3;
            unsigned long long src = cx.w1t_g +
                ((size_t)n * KSEG + (seg ? 1024 + ec : ec)) * 2ull + f4 * 16;
            CP16(stg + (seg ? ST_WS : ST_WB) + (uint32_t)(n * 64 + f4 * 16), src);
        }
        if (tid < 16) {                        // AM: permuted am chunk [4][32] fp16
            int q = tid >> 2, f4 = tid & 3;
            unsigned long long src = cx.amb_g + ((size_t)(cx.b0 + q) * EMB + ec) * 2ull + f4 * 16;
            CP16(stg + ST_AM + (uint32_t)(q * 64 + f4 * 16), src);
        }
    } else {
        const int pc = (c - 32) * 32;
#pragma unroll
        for (int it = 0; it < 2; it++) {       // A: pw values [256][32] fp16
            int id = tid + it * 512;
            int r = id >> 2, f4 = id & 3;
            int bq = r >> 6, a = r & 63; if (a >= cx.n_ants) a = cx.n_ants - 1;
            unsigned long long src = cx.pw_g +
                (((size_t)(cx.b0 + bq) * cx.n_ants + a) * PW + pc) * 2ull + f4 * 16;
            CP16(stg + ST_A + (uint32_t)(r * 80 + f4 * 16), src);
        }
        {                                      // B: W1p (permuted) into WB region
            int n = tid >> 2, f4 = tid & 3;
            unsigned long long src = cx.w1t_g + ((size_t)n * KSEG + 2048 + pc) * 2ull + f4 * 16;
            CP16(stg + ST_WB + (uint32_t)(n * 64 + f4 * 16), src);
        }
    }
}

__global__ __launch_bounds__(512, 1)
void pair_mma_kernel(const float* __restrict__ m_b,
                     const void*  __restrict__ top_idx,
                     const float* __restrict__ rough,
                     const float* __restrict__ W1,
                     const float* __restrict__ b1,
                     const float* __restrict__ W_out,
                     const float* __restrict__ b_out,
                     float* __restrict__ out,
                     int n_ants) {
    extern __shared__ char smem[];
    const uint32_t sbase = smem_u32(smem);
    const int tid  = threadIdx.x;
    const int lane = tid & 31;
    const int wid  = tid >> 5;
    const int t    = lane & 3;       // k lane within quad
    const int q    = lane >> 2;      // row/col lane (0..7)
    const int b0   = blockIdx.x * 4;
    const int mi   = wid & 3;        // m-tile: rows [64mi,64mi+64); == bq
    const int nh   = wid >> 2;       // n-quarter: cols [32nh,32nh+32)
    const int rb   = mi * 64, nb = nh * 32;

    int*   idx_s   = (int*)(smem + OFF_IDX);
    float* wout_s  = (float*)(smem + OFF_WOUT);
    float* aproj_s = (float*)(smem + OFF_APROJ);

    StageCtx cx;
    cx.allm_g = to_global(g_allm_h);
    cx.w1t_g  = to_global(g_W1Th);
    cx.pw_g   = to_global(g_pw_h);
    cx.amb_g  = to_global(g_amb_hp);
    cx.b0 = b0; cx.n_ants = n_ants;

    if (tid < 256) {
        int a = tid & 63; if (a >= n_ants) a = n_ants - 1;
        idx_s[tid] = load_idx(top_idx, (size_t)(b0 + (tid >> 6)) * n_ants + a, g_idx64);
    }
    if (tid < 128) wout_s[tid] = W_out[tid];
    __syncthreads();

    stage_chunk(0, sbase, idx_s, cx, tid); CP_COMMIT();
    stage_chunk(1, sbase, idx_s, cx, tid); CP_COMMIT();
    stage_chunk(2, sbase, idx_s, cx, tid); CP_COMMIT();

    // accumulators: 4 m-frags x 4 n-frags x 4 (fp32)
    float acc[4][4][4];
#pragma unroll
    for (int i = 0; i < 4; i++)
#pragma unroll
        for (int nf = 0; nf < 4; nf++)
#pragma unroll
            for (int r = 0; r < 4; r++) acc[i][nf][r] = 0.f;

    // aproj accumulator (exact fp32): thread owns (abq = tid>>7, an = tid&127)
    const int abq = tid >> 7, an = tid & 127;
    const float* ap_w  = W1 + an;
    const float* ap_am = m_b + (size_t)(b0 + abq) * EMB;
    float aproj_acc = 0.f;

    for (int c = 0; c < NCHUNK; c++) {
        CP_WAIT2();
        __syncthreads();                       // stage(c) ready

        const char* stp = smem + OFF_STAGE + (c % 3) * STAGE_B;
        const bool has_sim = (c < 32);

        // B'' fold in registers: bpp[nf] = {b0s0, b1s0, b0s1, b1s1} half2s
        uint32_t bpp[4][4];
        {
            uint4 am4 = make_uint4(0, 0, 0, 0);
            if (has_sim) am4 = *(const uint4*)(stp + ST_AM + mi * 64 + t * 16);
#pragma unroll
            for (int nf = 0; nf < 4; nf++) {
                int n = nb + nf * 8 + q;
                uint4 wb = *(const uint4*)(stp + ST_WB + n * 64 + t * 16);
                if (has_sim) {
                    uint4 ws = *(const uint4*)(stp + ST_WS + n * 64 + t * 16);
                    bpp[nf][0] = hfma2u(am4.x, ws.x, wb.x);
                    bpp[nf][1] = hfma2u(am4.y, ws.y, wb.y);
                    bpp[nf][2] = hfma2u(am4.z, ws.z, wb.z);
                    bpp[nf][3] = hfma2u(am4.w, ws.w, wb.w);
                } else {
                    bpp[nf][0] = wb.x; bpp[nf][1] = wb.y;
                    bpp[nf][2] = wb.z; bpp[nf][3] = wb.w;
                }
            }
        }

#pragma unroll
        for (int s = 0; s < 2; s++) {          // two k16 steps
            uint32_t a_[4][4];
#pragma unroll
            for (int i = 0; i < 4; i++) {
                const char* ap = stp + ST_A + (rb + 16 * i + q) * 80 + s * 32 + t * 4;
                a_[i][0] = *(const uint32_t*)(ap);
                a_[i][1] = *(const uint32_t*)(ap + 8 * 80);
                a_[i][2] = *(const uint32_t*)(ap + 16);
                a_[i][3] = *(const uint32_t*)(ap + 8 * 80 + 16);
            }
#pragma unroll
            for (int nf = 0; nf < 4; nf++) {
                uint32_t b0r = bpp[nf][2 * s], b1r = bpp[nf][2 * s + 1];
#pragma unroll
                for (int i = 0; i < 4; i++)
                    mma_f16(acc[i][nf], a_[i][0], a_[i][1], a_[i][2], a_[i][3], b0r, b1r);
            }
        }

        if (has_sim) {                          // interleaved aproj (coalesced LDG)
            const float* wrow = ap_w + (size_t)(c * 32) * HID;
            const float* amr2 = ap_am + c * 32;
#pragma unroll 8
            for (int kk = 0; kk < 32; kk++)
                aproj_acc += __ldg(amr2 + kk) * __ldg(wrow + (size_t)kk * HID);
        }
        __syncthreads();                        // done reading stage(c)

        if (c + 3 < NCHUNK) stage_chunk(c + 3, sbase, idx_s, cx, tid);
        CP_COMMIT();
    }

    // ---- epilogue ----
    aproj_s[tid] = aproj_acc + b1[an];          // tid == abq*128 + an
    __syncthreads();

    float* part = (float*)(smem + OFF_STAGE);   // [256][4] partials
    const float  bo  = __ldg(b_out);
    const float* apq = aproj_s + mi * 128;
#pragma unroll
    for (int i = 0; i < 4; i++) {
        float s0 = 0.f, s1 = 0.f;               // rows rb+16i+q, rb+16i+q+8
#pragma unroll
        for (int nf = 0; nf < 4; nf++) {
            int n0 = nb + nf * 8 + 2 * t, n1 = n0 + 1;
            float w0 = wout_s[n0], w1 = wout_s[n1];
            float ap0 = apq[n0], ap1 = apq[n1];
            float h;
            h = acc[i][nf][0] + ap0; h = fmaxf(h, 0.f) + 0.01f * fminf(h, 0.f); s0 += h * w0;
            h = acc[i][nf][1] + ap1; h = fmaxf(h, 0.f) + 0.01f * fminf(h, 0.f); s0 += h * w1;
            h = acc[i][nf][2] + ap0; h = fmaxf(h, 0.f) + 0.01f * fminf(h, 0.f); s1 += h * w0;
            h = acc[i][nf][3] + ap1; h = fmaxf(h, 0.f) + 0.01f * fminf(h, 0.f); s1 += h * w1;
        }
        s0 += __shfl_xor_sync(0xffffffffu, s0, 1);
        s0 += __shfl_xor_sync(0xffffffffu, s0, 2);
        s1 += __shfl_xor_sync(0xffffffffu, s1, 1);
        s1 += __shfl_xor_sync(0xffffffffu, s1, 2);
        if (t == 0) {
            part[(rb + 16 * i + q) * 4 + nh]     = s0;
            part[(rb + 16 * i + q + 8) * 4 + nh] = s1;
        }
    }
    __syncthreads();

    if (tid < 256) {
        float sc = part[tid * 4] + part[tid * 4 + 1] + part[tid * 4 + 2] + part[tid * 4 + 3];
        int a = tid & 63, bg = b0 + (tid >> 6);
        if (a < n_ants)
            out[(size_t)bg * (n_ants + 1) + 1 + a] =
                rough[(size_t)bg * n_ants + a] + bo + sc;
        if (a == 0) out[(size_t)bg * (n_ants + 1)] = EPSV;
    }
}

// -------------------- launch --------------------
extern "C" void kernel_launch(void* const* d_in, const int* in_sizes, int n_in,
                              void* d_out, int out_size) {
    const float* all_m = (const float*)d_in[0];
    const float* m_b   = (const float*)d_in[1];
    const float* pw    = (const float*)d_in[2];
    const void*  idx   = d_in[3];
    const float* rough = (const float*)d_in[4];
    const float* W1    = (const float*)d_in[5];
    const float* b1    = (const float*)d_in[6];
    const float* Wo    = (const float*)d_in[7];
    const float* bo    = (const float*)d_in[8];
    float* out = (float*)d_out;

    const int n_mentions = in_sizes[0] / EMB;  // 10000
    const int batch      = in_sizes[1] / EMB;  // 512
    const int n_ants     = in_sizes[3] / batch;// 50

    cudaFuncSetAttribute(pair_mma_kernel,
                         cudaFuncAttributeMaxDynamicSharedMemorySize, SMEM_TOTAL);

    prep_kernel<<<1184, 256>>>(all_m, m_b, pw, W1, (const unsigned*)idx, in_sizes[3],
                               n_mentions, batch, n_ants);
    pair_mma_kernel<<<batch / 4, 512, SMEM_TOTAL>>>(m_b, idx, rough,
                                                    W1, b1, Wo, bo, out, n_ants);
}